// round 12
// baseline (speedup 1.0000x reference)
#include <cuda_runtime.h>
#include <cuda_fp16.h>
#include <math.h>
#include <stdint.h>

#define B_ 1024
#define S_ 254
#define C_ 2
#define H_ 1024
#define NSTEPS 50
#define DT 0.02f

// ===================== helpers =============================================
__device__ __forceinline__ uint32_t smem_to_u32(const void* p) {
    uint32_t a;
    asm("{ .reg .u64 t; cvta.to.shared.u64 t, %1; cvt.u32.u64 %0, t; }" : "=r"(a) : "l"(p));
    return a;
}
#define CP_ASYNC16(dst, src) \
    asm volatile("cp.async.cg.shared.global [%0], [%1], 16;" :: "r"(dst), "l"(src) : "memory")
#define CP_COMMIT() asm volatile("cp.async.commit_group;" ::: "memory")
#define CP_WAIT1() asm volatile("cp.async.wait_group 1;" ::: "memory")

__device__ __forceinline__ void ldsm4(uint32_t* r, uint32_t addr) {
    asm volatile("ldmatrix.sync.aligned.m8n8.x4.shared.b16 {%0,%1,%2,%3}, [%4];"
        : "=r"(r[0]), "=r"(r[1]), "=r"(r[2]), "=r"(r[3]) : "r"(addr));
}
__device__ __forceinline__ void mma16816h(float* c, const uint32_t* a, const uint32_t* b) {
    asm volatile("mma.sync.aligned.m16n8k16.row.col.f32.f16.f16.f32 "
        "{%0,%1,%2,%3}, {%4,%5,%6,%7}, {%8,%9}, {%0,%1,%2,%3};"
        : "+f"(c[0]), "+f"(c[1]), "+f"(c[2]), "+f"(c[3])
        : "r"(a[0]), "r"(a[1]), "r"(a[2]), "r"(a[3]), "r"(b[0]), "r"(b[1]));
}

__device__ __forceinline__ float silu_f(float v) { return v / (1.0f + __expf(-v)); }

// ===================== scratch (device globals, no allocs) ==================
__device__ __half g_base0h[B_ * H_];
__device__ __half g_tvech[NSTEPS * H_];
__device__ __half g_w254h[H_];
__device__ __half g_w255h[H_];
__device__ float g_x[B_ * C_];
__device__ __half g_actA[B_ * H_];
__device__ __half g_actB[B_ * H_];
__device__ __half g_w16[3][H_ * H_];        // fp16 [N,K] transposed
__device__ float g_part[8 * 16 * 128 * 2];  // [mblock][nblock][row][c]

// ===================== weight transpose to fp16 (all 3 layers, z) ===========
__global__ void wconv_kernel(const float* __restrict__ W1,
                             const float* __restrict__ W2,
                             const float* __restrict__ W3,
                             __half* __restrict__ w16) {
    __shared__ float t[32][33];
    const float* W = (blockIdx.z == 0) ? W1 : (blockIdx.z == 1) ? W2 : W3;
    __half* dst = w16 + (size_t)blockIdx.z * H_ * H_;
    const int k0 = blockIdx.y * 32, n0 = blockIdx.x * 32;
    const int tx = threadIdx.x, ty = threadIdx.y;
    for (int i = ty; i < 32; i += 8)
        t[i][tx] = W[(size_t)(k0 + i) * H_ + n0 + tx];
    __syncthreads();
    for (int i = ty; i < 32; i += 8)
        dst[(size_t)(n0 + i) * H_ + k0 + tx] = __float2half_rn(t[tx][i]);
}

// ===================== w254/w255 fp16 conversion ============================
__global__ void wrow_kernel(const float* __restrict__ w254,
                            const float* __restrict__ w255,
                            __half* __restrict__ h254, __half* __restrict__ h255) {
    const int j = blockIdx.x * 256 + threadIdx.x;
    h254[j] = __float2half_rn(w254[j]);
    h255[j] = __float2half_rn(w255[j]);
}

// ===================== time-embedding contribution (fp16 out) ===============
__global__ __launch_bounds__(128) void tvec_kernel(const float* __restrict__ W0,
                                                   __half* __restrict__ tvech) {
    __shared__ float temb[64];
    const int step = blockIdx.x;
    const int tid = threadIdx.x;
    const float t = (float)step * DT;
    if (tid < 64) {
        int k = tid & 31;
        float freq = expf(-9.210340371976184f * (float)k / 31.0f);
        float ang = t * freq;
        temb[tid] = (tid < 32) ? sinf(ang) : cosf(ang);
    }
    __syncthreads();
    const int j = blockIdx.y * 128 + tid;
    float acc = 0.0f;
    #pragma unroll
    for (int k = 0; k < 64; k++)
        acc += temb[k] * W0[(size_t)(256 + k) * H_ + j];
    tvech[step * H_ + j] = __float2half_rn(acc);
}

// ===================== fp32 SGEMM for base0 (K=254, one-time, fp16 out) =====
#define BM 128
#define BN 64
#define BKK 16
__global__ __launch_bounds__(256) void sgemm_kernel(
    const float* __restrict__ A, int lda,
    const float* __restrict__ Bm, int ldb,
    const float* __restrict__ bias,
    __half* __restrict__ Cm, int ldc, int K)
{
    __shared__ __align__(16) float As[2][BKK][BM + 4];
    __shared__ __align__(16) float Bs[2][BKK][BN];
    const int tid = threadIdx.x;
    const int tx = tid & 15, ty = tid >> 4;
    const int row0 = blockIdx.y * BM, col0 = blockIdx.x * BN;
    const int m0 = ty * 8, n0 = tx * 4;
    const int arow = tid >> 2, akq = (tid & 3) * 4;
    const int bk = tid >> 4, bn = (tid & 15) * 4;

    float acc[8][4];
    #pragma unroll
    for (int i = 0; i < 8; i++)
        #pragma unroll
        for (int j = 0; j < 4; j++) acc[i][j] = 0.0f;
    float4 ra[2], rb;

    auto gload = [&](int kt) {
        const int kbase = kt * BKK;
        #pragma unroll
        for (int i = 0; i < 2; i++) {
            int r = arow + i * 64, k = kbase + akq;
            const float* p = A + (size_t)(row0 + r) * lda + k;
            float4 v;
            v.x = (k + 0 < K) ? p[0] : 0.0f;
            v.y = (k + 1 < K) ? p[1] : 0.0f;
            v.z = (k + 2 < K) ? p[2] : 0.0f;
            v.w = (k + 3 < K) ? p[3] : 0.0f;
            ra[i] = v;
        }
        int k = kbase + bk;
        const float* p = Bm + (size_t)k * ldb + col0 + bn;
        rb = (k < K) ? *reinterpret_cast<const float4*>(p) : make_float4(0, 0, 0, 0);
    };
    auto sstore = [&](int buf) {
        #pragma unroll
        for (int i = 0; i < 2; i++) {
            int r = arow + i * 64;
            As[buf][akq + 0][r] = ra[i].x;
            As[buf][akq + 1][r] = ra[i].y;
            As[buf][akq + 2][r] = ra[i].z;
            As[buf][akq + 3][r] = ra[i].w;
        }
        *reinterpret_cast<float4*>(&Bs[buf][bk][bn]) = rb;
    };

    const int ktiles = (K + BKK - 1) / BKK;
    gload(0); sstore(0); __syncthreads();
    for (int kt = 0; kt < ktiles; kt++) {
        const int buf = kt & 1;
        if (kt + 1 < ktiles) gload(kt + 1);
        #pragma unroll
        for (int kk = 0; kk < BKK; kk++) {
            float a[8], bv[4];
            #pragma unroll
            for (int i = 0; i < 8; i++) a[i] = As[buf][kk][m0 + i];
            #pragma unroll
            for (int j = 0; j < 4; j++) bv[j] = Bs[buf][kk][n0 + j];
            #pragma unroll
            for (int i = 0; i < 8; i++)
                #pragma unroll
                for (int j = 0; j < 4; j++)
                    acc[i][j] = fmaf(a[i], bv[j], acc[i][j]);
        }
        if (kt + 1 < ktiles) sstore(buf ^ 1);
        __syncthreads();
    }
    float bb[4];
    #pragma unroll
    for (int j = 0; j < 4; j++) bb[j] = bias[col0 + n0 + j];
    #pragma unroll
    for (int i = 0; i < 8; i++) {
        const int m = row0 + m0 + i;
        __half2 h01 = __floats2half2_rn(acc[i][0] + bb[0], acc[i][1] + bb[1]);
        __half2 h23 = __floats2half2_rn(acc[i][2] + bb[2], acc[i][3] + bb[3]);
        __half2* dst = reinterpret_cast<__half2*>(Cm + (size_t)m * ldc + col0 + n0);
        dst[0] = h01; dst[1] = h23;
    }
}

// ===================== fp16 HMMA GEMM common (BK=128, 3 stages) =============
// Stage layout: [A sub0 16K][A sub1 16K][B sub0 8K][B sub1 8K] = 48KB.
// Subtile s covers k = kt*128 + s*64 .. +63 with the old 64B-row swizzle.
#define GBM 128
#define GBN 64
#define GBK 128
#define GSTAGES 3
#define OFF_A 0
#define OFF_B 32768
#define STAGE_BYTES 49152
#define GSMEM_TOTAL (GSTAGES * STAGE_BYTES)

__device__ __forceinline__ uint32_t soff(int r, int ch) {
    return (uint32_t)(r * 128 + (((ch ^ r) & 7) << 4));
}

#define GEMM_MAINLOOP(A_, W_)                                                           \
    auto load_stage = [&](int kt) {                                                     \
        const uint32_t sb = sbase + (uint32_t)(kt % GSTAGES) * STAGE_BYTES;             \
        const int kb = kt * GBK;                                                        \
        _Pragma("unroll")                                                               \
        for (int s = 0; s < 2; s++)                                                     \
            _Pragma("unroll")                                                           \
            for (int i = 0; i < 4; i++) {                                               \
                int c = tid + i * 256;                                                  \
                int r = c >> 3, ch = c & 7;                                             \
                CP_ASYNC16(sb + OFF_A + s * 16384 + soff(r, ch),                        \
                           A_ + (size_t)(row0 + r) * H_ + kb + s * 64 + ch * 8);        \
            }                                                                           \
        _Pragma("unroll")                                                               \
        for (int s = 0; s < 2; s++)                                                     \
            _Pragma("unroll")                                                           \
            for (int i = 0; i < 2; i++) {                                               \
                int c = tid + i * 256;                                                  \
                int r = c >> 3, ch = c & 7;                                             \
                CP_ASYNC16(sb + OFF_B + s * 8192 + soff(r, ch),                         \
                           W_ + (size_t)(col0 + r) * H_ + kb + s * 64 + ch * 8);        \
            }                                                                           \
    };                                                                                  \
    const int a_r = wm * 32 + (lane & 15);                                              \
    const int a_half = lane >> 4;                                                       \
    const int b_r = wn * 32 + (lane & 7) + ((lane >> 4) << 3);                          \
    const int b_half = (lane >> 3) & 1;                                                 \
    load_stage(0); CP_COMMIT();                                                         \
    load_stage(1); CP_COMMIT();                                                         \
    uint32_t af[2][2][4];                                                               \
    uint32_t bf[2][2][4];                                                               \
    const int NKT = H_ / GBK;  /* 8 */                                                  \
    for (int kt = 0; kt < NKT; kt++) {                                                  \
        CP_WAIT1();                                                                     \
        __syncthreads();                                                                \
        const uint32_t sb = sbase + (uint32_t)(kt % GSTAGES) * STAGE_BYTES;             \
        _Pragma("unroll")                                                               \
        for (int mi = 0; mi < 2; mi++)                                                  \
            ldsm4(af[0][mi], sb + OFF_A + soff(a_r + mi * 16, a_half));                 \
        _Pragma("unroll")                                                               \
        for (int nt = 0; nt < 2; nt++)                                                  \
            ldsm4(bf[0][nt], sb + OFF_B + soff(b_r + nt * 16, b_half));                 \
        _Pragma("unroll")                                                               \
        for (int ks = 0; ks < 8; ks++) {                                                \
            const int cur = ks & 1, nxt = cur ^ 1;                                      \
            if (ks < 7) {                                                               \
                const int sub = (ks + 1) >> 2;                                          \
                const int cc = ((ks + 1) & 3) * 2;                                      \
                _Pragma("unroll")                                                       \
                for (int mi = 0; mi < 2; mi++)                                          \
                    ldsm4(af[nxt][mi], sb + OFF_A + sub * 16384                         \
                          + soff(a_r + mi * 16, cc + a_half));                          \
                _Pragma("unroll")                                                       \
                for (int nt = 0; nt < 2; nt++)                                          \
                    ldsm4(bf[nxt][nt], sb + OFF_B + sub * 8192                          \
                          + soff(b_r + nt * 16, cc + b_half));                          \
            }                                                                           \
            if (ks == 0) {                                                              \
                if (kt + 2 < NKT) load_stage(kt + 2);                                   \
                CP_COMMIT();                                                            \
            }                                                                           \
            _Pragma("unroll")                                                           \
            for (int mi = 0; mi < 2; mi++)                                              \
                _Pragma("unroll")                                                       \
                for (int ni = 0; ni < 4; ni++)                                          \
                    mma16816h(acc[mi][ni], af[cur][mi], &bf[cur][ni >> 1][(ni & 1) * 2]); \
        }                                                                               \
    }

// ---- variant 1: silu + fp16 store (layers 1, 2) ----
__global__ __launch_bounds__(256, 1) void gemm_hmma(
    const __half* __restrict__ A, const __half* __restrict__ W,
    const float* __restrict__ bias, __half* __restrict__ outC)
{
    extern __shared__ __align__(1024) char gs[];
    const uint32_t sbase = smem_to_u32(gs);
    const int tid = threadIdx.x;
    const int row0 = blockIdx.y * GBM;
    const int col0 = blockIdx.x * GBN;
    const int lane = tid & 31;
    const int wid = tid >> 5;
    const int wm = wid & 3;
    const int wn = wid >> 2;

    float acc[2][4][4];
    #pragma unroll
    for (int mi = 0; mi < 2; mi++)
        #pragma unroll
        for (int ni = 0; ni < 4; ni++)
            #pragma unroll
            for (int q = 0; q < 4; q++) acc[mi][ni][q] = 0.0f;

    GEMM_MAINLOOP(A, W)

    #pragma unroll
    for (int mi = 0; mi < 2; mi++) {
        const int r0g = row0 + wm * 32 + mi * 16 + (lane >> 2);
        #pragma unroll
        for (int ni = 0; ni < 4; ni++) {
            const int cg = col0 + wn * 32 + ni * 8 + (lane & 3) * 2;
            float2 bb = *reinterpret_cast<const float2*>(bias + cg);
            __half2 p0 = __floats2half2_rn(silu_f(acc[mi][ni][0] + bb.x),
                                           silu_f(acc[mi][ni][1] + bb.y));
            __half2 p1 = __floats2half2_rn(silu_f(acc[mi][ni][2] + bb.x),
                                           silu_f(acc[mi][ni][3] + bb.y));
            *reinterpret_cast<__half2*>(outC + (size_t)r0g * H_ + cg) = p0;
            *reinterpret_cast<__half2*>(outC + (size_t)(r0g + 8) * H_ + cg) = p1;
        }
    }
}

// ---- variant 2: layer 3 — silu then fold output head, write partials ----
__global__ __launch_bounds__(256, 1) void gemm_hmma_last(
    const __half* __restrict__ A, const __half* __restrict__ W,
    const float* __restrict__ bias, const float* __restrict__ W4,
    float* __restrict__ part)
{
    extern __shared__ __align__(1024) char gs[];
    __shared__ float spart[128 * 2];
    const uint32_t sbase = smem_to_u32(gs);
    const int tid = threadIdx.x;
    const int row0 = blockIdx.y * GBM;
    const int col0 = blockIdx.x * GBN;
    const int lane = tid & 31;
    const int wid = tid >> 5;
    const int wm = wid & 3;
    const int wn = wid >> 2;

    float acc[2][4][4];
    #pragma unroll
    for (int mi = 0; mi < 2; mi++)
        #pragma unroll
        for (int ni = 0; ni < 4; ni++)
            #pragma unroll
            for (int q = 0; q < 4; q++) acc[mi][ni][q] = 0.0f;

    GEMM_MAINLOOP(A, W)

    const float2* w4 = reinterpret_cast<const float2*>(W4);
    float sum[2][2][2];  // [mi][rhalf][c]
    #pragma unroll
    for (int mi = 0; mi < 2; mi++)
        #pragma unroll
        for (int rh = 0; rh < 2; rh++) { sum[mi][rh][0] = 0.0f; sum[mi][rh][1] = 0.0f; }

    #pragma unroll
    for (int mi = 0; mi < 2; mi++) {
        #pragma unroll
        for (int ni = 0; ni < 4; ni++) {
            const int cg = col0 + wn * 32 + ni * 8 + (lane & 3) * 2;
            float2 bb = *reinterpret_cast<const float2*>(bias + cg);
            float2 w0 = w4[cg], w1 = w4[cg + 1];
            float h00 = silu_f(acc[mi][ni][0] + bb.x);
            float h01 = silu_f(acc[mi][ni][1] + bb.y);
            float h10 = silu_f(acc[mi][ni][2] + bb.x);
            float h11 = silu_f(acc[mi][ni][3] + bb.y);
            sum[mi][0][0] += h00 * w0.x + h01 * w1.x;
            sum[mi][0][1] += h00 * w0.y + h01 * w1.y;
            sum[mi][1][0] += h10 * w0.x + h11 * w1.x;
            sum[mi][1][1] += h10 * w0.y + h11 * w1.y;
        }
    }
    #pragma unroll
    for (int mi = 0; mi < 2; mi++)
        #pragma unroll
        for (int rh = 0; rh < 2; rh++)
            #pragma unroll
            for (int c = 0; c < 2; c++) {
                float v = sum[mi][rh][c];
                v += __shfl_xor_sync(0xffffffffu, v, 1);
                v += __shfl_xor_sync(0xffffffffu, v, 2);
                sum[mi][rh][c] = v;
            }
    if (wn == 0 && (lane & 3) == 0) {
        #pragma unroll
        for (int mi = 0; mi < 2; mi++)
            #pragma unroll
            for (int rh = 0; rh < 2; rh++) {
                int r = wm * 32 + mi * 16 + rh * 8 + (lane >> 2);
                spart[r * 2 + 0] = sum[mi][rh][0];
                spart[r * 2 + 1] = sum[mi][rh][1];
            }
    }
    __syncthreads();
    if (wn == 1 && (lane & 3) == 0) {
        #pragma unroll
        for (int mi = 0; mi < 2; mi++)
            #pragma unroll
            for (int rh = 0; rh < 2; rh++) {
                int r = wm * 32 + mi * 16 + rh * 8 + (lane >> 2);
                spart[r * 2 + 0] += sum[mi][rh][0];
                spart[r * 2 + 1] += sum[mi][rh][1];
            }
    }
    __syncthreads();
    float* dst = part + ((size_t)(blockIdx.y * 16 + blockIdx.x) * 256);
    if (tid < 256) dst[tid] = spart[tid];
}

// ===================== quarter-row layer0 body (all-fp16 inputs) ============
__device__ __forceinline__ void layer0_quarter(
    const __half* __restrict__ base0h, const __half* __restrict__ tvech,
    const __half* __restrict__ h254, const __half* __restrict__ h255,
    int row, int g, float xb0, float xb1, __half* __restrict__ hOut)
{
    const uint4* bsrc = reinterpret_cast<const uint4*>(base0h + (size_t)row * H_);
    const uint4* tsrc = reinterpret_cast<const uint4*>(tvech);
    const uint4* asrc = reinterpret_cast<const uint4*>(h254);
    const uint4* csrc = reinterpret_cast<const uint4*>(h255);
    uint4 bh = bsrc[g], th = tsrc[g], ah = asrc[g], ch = csrc[g];
    uint4 o;
    const uint32_t* bw = &bh.x;
    const uint32_t* tw = &th.x;
    const uint32_t* aw = &ah.x;
    const uint32_t* cw = &ch.x;
    uint32_t* ow = &o.x;
    #pragma unroll
    for (int w = 0; w < 4; w++) {
        float2 b = __half22float2(*reinterpret_cast<const __half2*>(&bw[w]));
        float2 t = __half22float2(*reinterpret_cast<const __half2*>(&tw[w]));
        float2 a = __half22float2(*reinterpret_cast<const __half2*>(&aw[w]));
        float2 c = __half22float2(*reinterpret_cast<const __half2*>(&cw[w]));
        float v0 = silu_f(b.x + t.x + xb0 * a.x + xb1 * c.x);
        float v1 = silu_f(b.y + t.y + xb0 * a.y + xb1 * c.y);
        *reinterpret_cast<__half2*>(&ow[w]) = __floats2half2_rn(v0, v1);
    }
    reinterpret_cast<uint4*>(hOut + (size_t)row * H_)[g] = o;
}

// ===================== layer-0 activation (step 0 only) =====================
__global__ __launch_bounds__(256) void layer0_act(
    const __half* __restrict__ base0h, const __half* __restrict__ tvec_step,
    const __half* __restrict__ h254, const __half* __restrict__ h255,
    const float* __restrict__ x, __half* __restrict__ h)
{
    const int tid = threadIdx.x;
    const int lane = tid & 31;
    const int wid = tid >> 5;
    const int row = blockIdx.x * 2 + (wid >> 2);
    const float xv0 = x[2 * row];
    const float xv1 = x[2 * row + 1];
    const int g = (wid & 3) * 32 + lane;
    layer0_quarter(base0h, tvec_step, h254, h255, row, g, xv0, xv1, h);
}

// ===================== fused: partial-sum + Euler + next-step layer0 ========
__global__ __launch_bounds__(256) void step_fuse(
    const float* __restrict__ part,
    const float* __restrict__ b4,
    float* __restrict__ x,
    const __half* __restrict__ base0h, const __half* __restrict__ tvec_next,
    const __half* __restrict__ h254, const __half* __restrict__ h255,
    __half* __restrict__ hOut)
{
    const int tid = threadIdx.x;
    const int lane = tid & 31;
    const int wid = tid >> 5;
    const int rbase = blockIdx.x * 2;

    __shared__ float sx[2][2];

    if (wid < 2) {
        const int row = rbase + wid;
        const int by = row >> 7, rl = row & 127;
        float v0 = 0.0f, v1 = 0.0f;
        if (lane < 16) {
            float2 p = *reinterpret_cast<const float2*>(
                part + ((size_t)(by * 16 + lane) * 128 + rl) * 2);
            v0 = p.x; v1 = p.y;
        }
        #pragma unroll
        for (int o = 8; o > 0; o >>= 1) {
            v0 += __shfl_down_sync(0xffffffffu, v0, o);
            v1 += __shfl_down_sync(0xffffffffu, v1, o);
        }
        if (lane == 0) {
            v0 = x[2 * row]     + DT * (v0 + b4[0]);
            v1 = x[2 * row + 1] + DT * (v1 + b4[1]);
            x[2 * row] = v0; x[2 * row + 1] = v1;
            sx[wid][0] = v0; sx[wid][1] = v1;
        }
    }
    __syncthreads();

    const int rl = wid >> 2;
    const int row = rbase + rl;
    const float xv0 = sx[rl][0];
    const float xv1 = sx[rl][1];
    const int g = (wid & 3) * 32 + lane;
    layer0_quarter(base0h, tvec_next, h254, h255, row, g, xv0, xv1, hOut);
}

// ===================== final: partial-sum + Euler -> out ====================
__global__ __launch_bounds__(256) void out_euler(
    const float* __restrict__ part,
    const float* __restrict__ b4,
    const float* __restrict__ x, float* __restrict__ out)
{
    const int tid = threadIdx.x;
    const int lane = tid & 31;
    const int wid = tid >> 5;
    const int row = blockIdx.x * 8 + wid;
    const int by = row >> 7, rl = row & 127;
    float v0 = 0.0f, v1 = 0.0f;
    if (lane < 16) {
        float2 p = *reinterpret_cast<const float2*>(
            part + ((size_t)(by * 16 + lane) * 128 + rl) * 2);
        v0 = p.x; v1 = p.y;
    }
    #pragma unroll
    for (int o = 8; o > 0; o >>= 1) {
        v0 += __shfl_down_sync(0xffffffffu, v0, o);
        v1 += __shfl_down_sync(0xffffffffu, v1, o);
    }
    if (lane == 0) {
        out[2 * row]     = x[2 * row]     + DT * (v0 + b4[0]);
        out[2 * row + 1] = x[2 * row + 1] + DT * (v1 + b4[1]);
    }
}

// ===================== host side ============================================
extern "C" void kernel_launch(void* const* d_in, const int* in_sizes, int n_in,
                              void* d_out, int out_size)
{
    const float* state = (const float*)d_in[0];
    const float* x0    = (const float*)d_in[1];
    const float* W0    = (const float*)d_in[2];
    const float* b0    = (const float*)d_in[3];
    const float* W1    = (const float*)d_in[4];
    const float* b1    = (const float*)d_in[5];
    const float* W2    = (const float*)d_in[6];
    const float* b2    = (const float*)d_in[7];
    const float* W3    = (const float*)d_in[8];
    const float* b3    = (const float*)d_in[9];
    const float* W4    = (const float*)d_in[10];
    const float* b4    = (const float*)d_in[11];
    float* out = (float*)d_out;

    float *xp, *partp;
    __half *base0h, *tvech, *h254, *h255, *actA, *actB, *w16;
    cudaGetSymbolAddress((void**)&base0h, g_base0h);
    cudaGetSymbolAddress((void**)&tvech,  g_tvech);
    cudaGetSymbolAddress((void**)&h254,   g_w254h);
    cudaGetSymbolAddress((void**)&h255,   g_w255h);
    cudaGetSymbolAddress((void**)&xp,     g_x);
    cudaGetSymbolAddress((void**)&actA,   g_actA);
    cudaGetSymbolAddress((void**)&actB,   g_actB);
    cudaGetSymbolAddress((void**)&w16,    g_w16);
    cudaGetSymbolAddress((void**)&partp,  g_part);

    static bool attr_set = false;
    if (!attr_set) {
        cudaFuncSetAttribute(gemm_hmma, cudaFuncAttributeMaxDynamicSharedMemorySize,
                             GSMEM_TOTAL);
        cudaFuncSetAttribute(gemm_hmma_last, cudaFuncAttributeMaxDynamicSharedMemorySize,
                             GSMEM_TOTAL);
        attr_set = true;
    }

    // one-time prep
    cudaMemcpyAsync(xp, x0, B_ * C_ * sizeof(float), cudaMemcpyDeviceToDevice);
    wconv_kernel<<<dim3(32, 32, 3), dim3(32, 8)>>>(W1, W2, W3, w16);
    tvec_kernel<<<dim3(NSTEPS, 8), 128>>>(W0, tvech);
    wrow_kernel<<<4, 256>>>(W0 + (size_t)254 * H_, W0 + (size_t)255 * H_, h254, h255);
    sgemm_kernel<<<dim3(H_ / BN, B_ / BM), 256>>>(state, S_, W0, H_, b0, base0h, H_, S_);

    __half* wl0 = w16 + 0 * (size_t)H_ * H_;
    __half* wl1 = w16 + 1 * (size_t)H_ * H_;
    __half* wl2 = w16 + 2 * (size_t)H_ * H_;

    dim3 ggrid(H_ / GBN, B_ / GBM);  // (16, 8) = 128 CTAs
    layer0_act<<<B_ / 2, 256>>>(base0h, tvech, h254, h255, xp, actA);
    for (int i = 0; i < NSTEPS; i++) {
        gemm_hmma<<<ggrid, 256, GSMEM_TOTAL>>>(actA, wl0, b1, actB);
        gemm_hmma<<<ggrid, 256, GSMEM_TOTAL>>>(actB, wl1, b2, actA);
        gemm_hmma_last<<<ggrid, 256, GSMEM_TOTAL>>>(actA, wl2, b3, W4, partp);
        if (i + 1 < NSTEPS) {
            step_fuse<<<B_ / 2, 256>>>(partp, b4, xp, base0h,
                                       tvech + (size_t)(i + 1) * H_, h254, h255, actA);
        } else {
            out_euler<<<B_ / 8, 256>>>(partp, b4, xp, out);
        }
    }
}

// round 13
// speedup vs baseline: 1.1748x; 1.1748x over previous
#include <cuda_runtime.h>
#include <cuda_fp16.h>
#include <math.h>
#include <stdint.h>

#define B_ 1024
#define S_ 254
#define C_ 2
#define H_ 1024
#define NSTEPS 50
#define DT 0.02f

// ===================== helpers =============================================
__device__ __forceinline__ uint32_t smem_to_u32(const void* p) {
    uint32_t a;
    asm("{ .reg .u64 t; cvta.to.shared.u64 t, %1; cvt.u32.u64 %0, t; }" : "=r"(a) : "l"(p));
    return a;
}
#define CP_ASYNC16(dst, src) \
    asm volatile("cp.async.cg.shared.global [%0], [%1], 16;" :: "r"(dst), "l"(src) : "memory")
#define CP_COMMIT() asm volatile("cp.async.commit_group;" ::: "memory")
#define CP_WAIT1() asm volatile("cp.async.wait_group 1;" ::: "memory")

// PDL
#define GDC_WAIT()   asm volatile("griddepcontrol.wait;" ::: "memory")
#define GDC_LAUNCH() asm volatile("griddepcontrol.launch_dependents;" ::: "memory")

__device__ __forceinline__ void ldsm4(uint32_t* r, uint32_t addr) {
    asm volatile("ldmatrix.sync.aligned.m8n8.x4.shared.b16 {%0,%1,%2,%3}, [%4];"
        : "=r"(r[0]), "=r"(r[1]), "=r"(r[2]), "=r"(r[3]) : "r"(addr));
}
__device__ __forceinline__ void mma16816h(float* c, const uint32_t* a, const uint32_t* b) {
    asm volatile("mma.sync.aligned.m16n8k16.row.col.f32.f16.f16.f32 "
        "{%0,%1,%2,%3}, {%4,%5,%6,%7}, {%8,%9}, {%0,%1,%2,%3};"
        : "+f"(c[0]), "+f"(c[1]), "+f"(c[2]), "+f"(c[3])
        : "r"(a[0]), "r"(a[1]), "r"(a[2]), "r"(a[3]), "r"(b[0]), "r"(b[1]));
}

__device__ __forceinline__ float silu_f(float v) { return v / (1.0f + __expf(-v)); }

// ===================== scratch (device globals, no allocs) ==================
__device__ __half g_base0h[B_ * H_];
__device__ __half g_tvech[NSTEPS * H_];
__device__ __half g_w254h[H_];
__device__ __half g_w255h[H_];
__device__ float g_x[B_ * C_];
__device__ __half g_actA[B_ * H_];
__device__ __half g_actB[B_ * H_];
__device__ __half g_w16[3][H_ * H_];        // fp16 [N,K] transposed
__device__ float g_part[8 * 16 * 128 * 2];  // [mblock][nblock][row][c]

// ===================== weight transpose to fp16 (all 3 layers, z) ===========
__global__ void wconv_kernel(const float* __restrict__ W1,
                             const float* __restrict__ W2,
                             const float* __restrict__ W3,
                             __half* __restrict__ w16) {
    __shared__ float t[32][33];
    const float* W = (blockIdx.z == 0) ? W1 : (blockIdx.z == 1) ? W2 : W3;
    __half* dst = w16 + (size_t)blockIdx.z * H_ * H_;
    const int k0 = blockIdx.y * 32, n0 = blockIdx.x * 32;
    const int tx = threadIdx.x, ty = threadIdx.y;
    for (int i = ty; i < 32; i += 8)
        t[i][tx] = W[(size_t)(k0 + i) * H_ + n0 + tx];
    __syncthreads();
    for (int i = ty; i < 32; i += 8)
        dst[(size_t)(n0 + i) * H_ + k0 + tx] = __float2half_rn(t[tx][i]);
}

// ===================== w254/w255 fp16 conversion ============================
__global__ void wrow_kernel(const float* __restrict__ w254,
                            const float* __restrict__ w255,
                            __half* __restrict__ h254, __half* __restrict__ h255) {
    const int j = blockIdx.x * 256 + threadIdx.x;
    h254[j] = __float2half_rn(w254[j]);
    h255[j] = __float2half_rn(w255[j]);
}

// ===================== time-embedding contribution (fp16 out) ===============
__global__ __launch_bounds__(128) void tvec_kernel(const float* __restrict__ W0,
                                                   __half* __restrict__ tvech) {
    __shared__ float temb[64];
    const int step = blockIdx.x;
    const int tid = threadIdx.x;
    const float t = (float)step * DT;
    if (tid < 64) {
        int k = tid & 31;
        float freq = expf(-9.210340371976184f * (float)k / 31.0f);
        float ang = t * freq;
        temb[tid] = (tid < 32) ? sinf(ang) : cosf(ang);
    }
    __syncthreads();
    const int j = blockIdx.y * 128 + tid;
    float acc = 0.0f;
    #pragma unroll
    for (int k = 0; k < 64; k++)
        acc += temb[k] * W0[(size_t)(256 + k) * H_ + j];
    tvech[step * H_ + j] = __float2half_rn(acc);
}

// ===================== fp32 SGEMM for base0 (K=254, one-time, fp16 out) =====
#define BM 128
#define BN 64
#define BKK 16
__global__ __launch_bounds__(256) void sgemm_kernel(
    const float* __restrict__ A, int lda,
    const float* __restrict__ Bm, int ldb,
    const float* __restrict__ bias,
    __half* __restrict__ Cm, int ldc, int K)
{
    __shared__ __align__(16) float As[2][BKK][BM + 4];
    __shared__ __align__(16) float Bs[2][BKK][BN];
    const int tid = threadIdx.x;
    const int tx = tid & 15, ty = tid >> 4;
    const int row0 = blockIdx.y * BM, col0 = blockIdx.x * BN;
    const int m0 = ty * 8, n0 = tx * 4;
    const int arow = tid >> 2, akq = (tid & 3) * 4;
    const int bk = tid >> 4, bn = (tid & 15) * 4;

    float acc[8][4];
    #pragma unroll
    for (int i = 0; i < 8; i++)
        #pragma unroll
        for (int j = 0; j < 4; j++) acc[i][j] = 0.0f;
    float4 ra[2], rb;

    auto gload = [&](int kt) {
        const int kbase = kt * BKK;
        #pragma unroll
        for (int i = 0; i < 2; i++) {
            int r = arow + i * 64, k = kbase + akq;
            const float* p = A + (size_t)(row0 + r) * lda + k;
            float4 v;
            v.x = (k + 0 < K) ? p[0] : 0.0f;
            v.y = (k + 1 < K) ? p[1] : 0.0f;
            v.z = (k + 2 < K) ? p[2] : 0.0f;
            v.w = (k + 3 < K) ? p[3] : 0.0f;
            ra[i] = v;
        }
        int k = kbase + bk;
        const float* p = Bm + (size_t)k * ldb + col0 + bn;
        rb = (k < K) ? *reinterpret_cast<const float4*>(p) : make_float4(0, 0, 0, 0);
    };
    auto sstore = [&](int buf) {
        #pragma unroll
        for (int i = 0; i < 2; i++) {
            int r = arow + i * 64;
            As[buf][akq + 0][r] = ra[i].x;
            As[buf][akq + 1][r] = ra[i].y;
            As[buf][akq + 2][r] = ra[i].z;
            As[buf][akq + 3][r] = ra[i].w;
        }
        *reinterpret_cast<float4*>(&Bs[buf][bk][bn]) = rb;
    };

    const int ktiles = (K + BKK - 1) / BKK;
    gload(0); sstore(0); __syncthreads();
    for (int kt = 0; kt < ktiles; kt++) {
        const int buf = kt & 1;
        if (kt + 1 < ktiles) gload(kt + 1);
        #pragma unroll
        for (int kk = 0; kk < BKK; kk++) {
            float a[8], bv[4];
            #pragma unroll
            for (int i = 0; i < 8; i++) a[i] = As[buf][kk][m0 + i];
            #pragma unroll
            for (int j = 0; j < 4; j++) bv[j] = Bs[buf][kk][n0 + j];
            #pragma unroll
            for (int i = 0; i < 8; i++)
                #pragma unroll
                for (int j = 0; j < 4; j++)
                    acc[i][j] = fmaf(a[i], bv[j], acc[i][j]);
        }
        if (kt + 1 < ktiles) sstore(buf ^ 1);
        __syncthreads();
    }
    float bb[4];
    #pragma unroll
    for (int j = 0; j < 4; j++) bb[j] = bias[col0 + n0 + j];
    #pragma unroll
    for (int i = 0; i < 8; i++) {
        const int m = row0 + m0 + i;
        __half2 h01 = __floats2half2_rn(acc[i][0] + bb[0], acc[i][1] + bb[1]);
        __half2 h23 = __floats2half2_rn(acc[i][2] + bb[2], acc[i][3] + bb[3]);
        __half2* dst = reinterpret_cast<__half2*>(Cm + (size_t)m * ldc + col0 + n0);
        dst[0] = h01; dst[1] = h23;
    }
}

// ===================== fp16 HMMA GEMM common (BK=64, 3 stages) ==============
#define GBM 128
#define GBN 64
#define GBK 64
#define GSTAGES 3
#define OFF_A 0
#define OFF_B 16384
#define STAGE_BYTES 24576
#define GSMEM_TOTAL (GSTAGES * STAGE_BYTES)

__device__ __forceinline__ uint32_t soff(int r, int ch) {
    return (uint32_t)(r * 128 + (((ch ^ r) & 7) << 4));
}

// Consumer side: weights (B) prefetched BEFORE griddepcontrol.wait; A after.
#define GEMM_MAINLOOP(A_, W_)                                                           \
    auto load_A = [&](int kt) {                                                         \
        const uint32_t sb = sbase + (uint32_t)(kt % GSTAGES) * STAGE_BYTES;             \
        const int kb = kt * GBK;                                                        \
        _Pragma("unroll")                                                               \
        for (int i = 0; i < 4; i++) {                                                   \
            int c = tid + i * 256;                                                      \
            int r = c >> 3, ch = c & 7;                                                 \
            CP_ASYNC16(sb + OFF_A + soff(r, ch), A_ + (size_t)(row0 + r) * H_ + kb + ch * 8); \
        }                                                                               \
    };                                                                                  \
    auto load_B = [&](int kt) {                                                         \
        const uint32_t sb = sbase + (uint32_t)(kt % GSTAGES) * STAGE_BYTES;             \
        const int kb = kt * GBK;                                                        \
        _Pragma("unroll")                                                               \
        for (int i = 0; i < 2; i++) {                                                   \
            int c = tid + i * 256;                                                      \
            int r = c >> 3, ch = c & 7;                                                 \
            CP_ASYNC16(sb + OFF_B + soff(r, ch), W_ + (size_t)(col0 + r) * H_ + kb + ch * 8); \
        }                                                                               \
    };                                                                                  \
    const int a_r = wm * 32 + (lane & 15);                                              \
    const int a_half = lane >> 4;                                                       \
    const int b_r = wn * 32 + (lane & 7) + ((lane >> 4) << 3);                          \
    const int b_half = (lane >> 3) & 1;                                                 \
    load_B(0); load_B(1);          /* weights: independent of predecessor */            \
    GDC_WAIT();                    /* block until predecessor grid flushed */           \
    load_A(0); CP_COMMIT();        /* group0 = B0,B1,A0 */                              \
    load_A(1); CP_COMMIT();        /* group1 = A1 */                                    \
    uint32_t af[2][2][4];                                                               \
    uint32_t bf[2][2][4];                                                               \
    const int NKT = H_ / GBK;  /* 16 */                                                 \
    for (int kt = 0; kt < NKT; kt++) {                                                  \
        CP_WAIT1();                                                                     \
        __syncthreads();                                                                \
        const uint32_t sb = sbase + (uint32_t)(kt % GSTAGES) * STAGE_BYTES;             \
        _Pragma("unroll")                                                               \
        for (int mi = 0; mi < 2; mi++)                                                  \
            ldsm4(af[0][mi], sb + OFF_A + soff(a_r + mi * 16, a_half));                 \
        _Pragma("unroll")                                                               \
        for (int nt = 0; nt < 2; nt++)                                                  \
            ldsm4(bf[0][nt], sb + OFF_B + soff(b_r + nt * 16, b_half));                 \
        _Pragma("unroll")                                                               \
        for (int ks = 0; ks < 4; ks++) {                                                \
            const int cur = ks & 1, nxt = cur ^ 1;                                      \
            if (ks < 3) {                                                               \
                const int ch = (ks + 1) * 2;                                            \
                _Pragma("unroll")                                                       \
                for (int mi = 0; mi < 2; mi++)                                          \
                    ldsm4(af[nxt][mi], sb + OFF_A + soff(a_r + mi * 16, ch + a_half));  \
                _Pragma("unroll")                                                       \
                for (int nt = 0; nt < 2; nt++)                                          \
                    ldsm4(bf[nxt][nt], sb + OFF_B + soff(b_r + nt * 16, ch + b_half));  \
            }                                                                           \
            if (ks == 0) {                                                              \
                if (kt + 2 < NKT) { load_A(kt + 2); load_B(kt + 2); }                   \
                CP_COMMIT();                                                            \
            }                                                                           \
            _Pragma("unroll")                                                           \
            for (int mi = 0; mi < 2; mi++)                                              \
                _Pragma("unroll")                                                       \
                for (int ni = 0; ni < 4; ni++)                                          \
                    mma16816h(acc[mi][ni], af[cur][mi], &bf[cur][ni >> 1][(ni & 1) * 2]); \
        }                                                                               \
    }                                                                                   \
    GDC_LAUNCH();   /* co-residency window = epilogue only */

// ---- variant 1: silu + fp16 store (layers 1, 2) ----
__global__ __launch_bounds__(256, 1) void gemm_hmma(
    const __half* __restrict__ A, const __half* __restrict__ W,
    const float* __restrict__ bias, __half* __restrict__ outC)
{
    extern __shared__ __align__(1024) char gs[];
    const uint32_t sbase = smem_to_u32(gs);
    const int tid = threadIdx.x;
    const int row0 = blockIdx.y * GBM;
    const int col0 = blockIdx.x * GBN;
    const int lane = tid & 31;
    const int wid = tid >> 5;
    const int wm = wid & 3;
    const int wn = wid >> 2;

    float acc[2][4][4];
    #pragma unroll
    for (int mi = 0; mi < 2; mi++)
        #pragma unroll
        for (int ni = 0; ni < 4; ni++)
            #pragma unroll
            for (int q = 0; q < 4; q++) acc[mi][ni][q] = 0.0f;

    GEMM_MAINLOOP(A, W)

    #pragma unroll
    for (int mi = 0; mi < 2; mi++) {
        const int r0g = row0 + wm * 32 + mi * 16 + (lane >> 2);
        #pragma unroll
        for (int ni = 0; ni < 4; ni++) {
            const int cg = col0 + wn * 32 + ni * 8 + (lane & 3) * 2;
            float2 bb = *reinterpret_cast<const float2*>(bias + cg);
            __half2 p0 = __floats2half2_rn(silu_f(acc[mi][ni][0] + bb.x),
                                           silu_f(acc[mi][ni][1] + bb.y));
            __half2 p1 = __floats2half2_rn(silu_f(acc[mi][ni][2] + bb.x),
                                           silu_f(acc[mi][ni][3] + bb.y));
            *reinterpret_cast<__half2*>(outC + (size_t)r0g * H_ + cg) = p0;
            *reinterpret_cast<__half2*>(outC + (size_t)(r0g + 8) * H_ + cg) = p1;
        }
    }
}

// ---- variant 2: layer 3 — silu then fold output head, write partials ----
__global__ __launch_bounds__(256, 1) void gemm_hmma_last(
    const __half* __restrict__ A, const __half* __restrict__ W,
    const float* __restrict__ bias, const float* __restrict__ W4,
    float* __restrict__ part)
{
    extern __shared__ __align__(1024) char gs[];
    __shared__ float spart[128 * 2];
    const uint32_t sbase = smem_to_u32(gs);
    const int tid = threadIdx.x;
    const int row0 = blockIdx.y * GBM;
    const int col0 = blockIdx.x * GBN;
    const int lane = tid & 31;
    const int wid = tid >> 5;
    const int wm = wid & 3;
    const int wn = wid >> 2;

    float acc[2][4][4];
    #pragma unroll
    for (int mi = 0; mi < 2; mi++)
        #pragma unroll
        for (int ni = 0; ni < 4; ni++)
            #pragma unroll
            for (int q = 0; q < 4; q++) acc[mi][ni][q] = 0.0f;

    GEMM_MAINLOOP(A, W)

    const float2* w4 = reinterpret_cast<const float2*>(W4);
    float sum[2][2][2];  // [mi][rhalf][c]
    #pragma unroll
    for (int mi = 0; mi < 2; mi++)
        #pragma unroll
        for (int rh = 0; rh < 2; rh++) { sum[mi][rh][0] = 0.0f; sum[mi][rh][1] = 0.0f; }

    #pragma unroll
    for (int mi = 0; mi < 2; mi++) {
        #pragma unroll
        for (int ni = 0; ni < 4; ni++) {
            const int cg = col0 + wn * 32 + ni * 8 + (lane & 3) * 2;
            float2 bb = *reinterpret_cast<const float2*>(bias + cg);
            float2 w0 = w4[cg], w1 = w4[cg + 1];
            float h00 = silu_f(acc[mi][ni][0] + bb.x);
            float h01 = silu_f(acc[mi][ni][1] + bb.y);
            float h10 = silu_f(acc[mi][ni][2] + bb.x);
            float h11 = silu_f(acc[mi][ni][3] + bb.y);
            sum[mi][0][0] += h00 * w0.x + h01 * w1.x;
            sum[mi][0][1] += h00 * w0.y + h01 * w1.y;
            sum[mi][1][0] += h10 * w0.x + h11 * w1.x;
            sum[mi][1][1] += h10 * w0.y + h11 * w1.y;
        }
    }
    #pragma unroll
    for (int mi = 0; mi < 2; mi++)
        #pragma unroll
        for (int rh = 0; rh < 2; rh++)
            #pragma unroll
            for (int c = 0; c < 2; c++) {
                float v = sum[mi][rh][c];
                v += __shfl_xor_sync(0xffffffffu, v, 1);
                v += __shfl_xor_sync(0xffffffffu, v, 2);
                sum[mi][rh][c] = v;
            }
    if (wn == 0 && (lane & 3) == 0) {
        #pragma unroll
        for (int mi = 0; mi < 2; mi++)
            #pragma unroll
            for (int rh = 0; rh < 2; rh++) {
                int r = wm * 32 + mi * 16 + rh * 8 + (lane >> 2);
                spart[r * 2 + 0] = sum[mi][rh][0];
                spart[r * 2 + 1] = sum[mi][rh][1];
            }
    }
    __syncthreads();
    if (wn == 1 && (lane & 3) == 0) {
        #pragma unroll
        for (int mi = 0; mi < 2; mi++)
            #pragma unroll
            for (int rh = 0; rh < 2; rh++) {
                int r = wm * 32 + mi * 16 + rh * 8 + (lane >> 2);
                spart[r * 2 + 0] += sum[mi][rh][0];
                spart[r * 2 + 1] += sum[mi][rh][1];
            }
    }
    __syncthreads();
    float* dst = part + ((size_t)(blockIdx.y * 16 + blockIdx.x) * 256);
    if (tid < 256) dst[tid] = spart[tid];
}

// ===================== quarter-row layer0 body (all-fp16 inputs) ============
__device__ __forceinline__ void layer0_quarter(
    const __half* __restrict__ base0h, const __half* __restrict__ tvech,
    const __half* __restrict__ h254, const __half* __restrict__ h255,
    int row, int g, float xb0, float xb1, __half* __restrict__ hOut)
{
    const uint4* bsrc = reinterpret_cast<const uint4*>(base0h + (size_t)row * H_);
    const uint4* tsrc = reinterpret_cast<const uint4*>(tvech);
    const uint4* asrc = reinterpret_cast<const uint4*>(h254);
    const uint4* csrc = reinterpret_cast<const uint4*>(h255);
    uint4 bh = bsrc[g], th = tsrc[g], ah = asrc[g], ch = csrc[g];
    uint4 o;
    const uint32_t* bw = &bh.x;
    const uint32_t* tw = &th.x;
    const uint32_t* aw = &ah.x;
    const uint32_t* cw = &ch.x;
    uint32_t* ow = &o.x;
    #pragma unroll
    for (int w = 0; w < 4; w++) {
        float2 b = __half22float2(*reinterpret_cast<const __half2*>(&bw[w]));
        float2 t = __half22float2(*reinterpret_cast<const __half2*>(&tw[w]));
        float2 a = __half22float2(*reinterpret_cast<const __half2*>(&aw[w]));
        float2 c = __half22float2(*reinterpret_cast<const __half2*>(&cw[w]));
        float v0 = silu_f(b.x + t.x + xb0 * a.x + xb1 * c.x);
        float v1 = silu_f(b.y + t.y + xb0 * a.y + xb1 * c.y);
        *reinterpret_cast<__half2*>(&ow[w]) = __floats2half2_rn(v0, v1);
    }
    reinterpret_cast<uint4*>(hOut + (size_t)row * H_)[g] = o;
}

// ===================== layer-0 activation (step 0 only) =====================
__global__ __launch_bounds__(256) void layer0_act(
    const __half* __restrict__ base0h, const __half* __restrict__ tvec_step,
    const __half* __restrict__ h254, const __half* __restrict__ h255,
    const float* __restrict__ x, __half* __restrict__ h)
{
    const int tid = threadIdx.x;
    const int lane = tid & 31;
    const int wid = tid >> 5;
    const int row = blockIdx.x * 2 + (wid >> 2);
    const float xv0 = x[2 * row];
    const float xv1 = x[2 * row + 1];
    const int g = (wid & 3) * 32 + lane;
    layer0_quarter(base0h, tvec_step, h254, h255, row, g, xv0, xv1, h);
}

// ===================== fused: partial-sum + Euler + next-step layer0 ========
__global__ __launch_bounds__(256) void step_fuse(
    const float* __restrict__ part,
    const float* __restrict__ b4,
    float* __restrict__ x,
    const __half* __restrict__ base0h, const __half* __restrict__ tvec_next,
    const __half* __restrict__ h254, const __half* __restrict__ h255,
    __half* __restrict__ hOut)
{
    GDC_WAIT();      // predecessor (gemm_hmma_last) partials visible
    GDC_LAUNCH();    // successor's weight prefetch may begin; its A-loads wait
    const int tid = threadIdx.x;
    const int lane = tid & 31;
    const int wid = tid >> 5;
    const int rbase = blockIdx.x * 2;

    __shared__ float sx[2][2];

    if (wid < 2) {
        const int row = rbase + wid;
        const int by = row >> 7, rl = row & 127;
        float v0 = 0.0f, v1 = 0.0f;
        if (lane < 16) {
            float2 p = *reinterpret_cast<const float2*>(
                part + ((size_t)(by * 16 + lane) * 128 + rl) * 2);
            v0 = p.x; v1 = p.y;
        }
        #pragma unroll
        for (int o = 8; o > 0; o >>= 1) {
            v0 += __shfl_down_sync(0xffffffffu, v0, o);
            v1 += __shfl_down_sync(0xffffffffu, v1, o);
        }
        if (lane == 0) {
            v0 = x[2 * row]     + DT * (v0 + b4[0]);
            v1 = x[2 * row + 1] + DT * (v1 + b4[1]);
            x[2 * row] = v0; x[2 * row + 1] = v1;
            sx[wid][0] = v0; sx[wid][1] = v1;
        }
    }
    __syncthreads();

    const int rl = wid >> 2;
    const int row = rbase + rl;
    const float xv0 = sx[rl][0];
    const float xv1 = sx[rl][1];
    const int g = (wid & 3) * 32 + lane;
    layer0_quarter(base0h, tvec_next, h254, h255, row, g, xv0, xv1, hOut);
}

// ===================== final: partial-sum + Euler -> out ====================
__global__ __launch_bounds__(256) void out_euler(
    const float* __restrict__ part,
    const float* __restrict__ b4,
    const float* __restrict__ x, float* __restrict__ out)
{
    GDC_WAIT();
    const int tid = threadIdx.x;
    const int lane = tid & 31;
    const int wid = tid >> 5;
    const int row = blockIdx.x * 8 + wid;
    const int by = row >> 7, rl = row & 127;
    float v0 = 0.0f, v1 = 0.0f;
    if (lane < 16) {
        float2 p = *reinterpret_cast<const float2*>(
            part + ((size_t)(by * 16 + lane) * 128 + rl) * 2);
        v0 = p.x; v1 = p.y;
    }
    #pragma unroll
    for (int o = 8; o > 0; o >>= 1) {
        v0 += __shfl_down_sync(0xffffffffu, v0, o);
        v1 += __shfl_down_sync(0xffffffffu, v1, o);
    }
    if (lane == 0) {
        out[2 * row]     = x[2 * row]     + DT * (v0 + b4[0]);
        out[2 * row + 1] = x[2 * row + 1] + DT * (v1 + b4[1]);
    }
}

// ===================== host side ============================================
template <typename KernelT, typename... Args>
static void launch_pdl(KernelT k, dim3 g, dim3 b, size_t smem, Args... args) {
    cudaLaunchConfig_t cfg = {};
    cfg.gridDim = g;
    cfg.blockDim = b;
    cfg.dynamicSmemBytes = smem;
    cfg.stream = 0;
    cudaLaunchAttribute at[1];
    at[0].id = cudaLaunchAttributeProgrammaticStreamSerialization;
    at[0].val.programmaticStreamSerializationAllowed = 1;
    cfg.attrs = at;
    cfg.numAttrs = 1;
    cudaLaunchKernelEx(&cfg, k, args...);
}

extern "C" void kernel_launch(void* const* d_in, const int* in_sizes, int n_in,
                              void* d_out, int out_size)
{
    const float* state = (const float*)d_in[0];
    const float* x0    = (const float*)d_in[1];
    const float* W0    = (const float*)d_in[2];
    const float* b0    = (const float*)d_in[3];
    const float* W1    = (const float*)d_in[4];
    const float* b1    = (const float*)d_in[5];
    const float* W2    = (const float*)d_in[6];
    const float* b2    = (const float*)d_in[7];
    const float* W3    = (const float*)d_in[8];
    const float* b3    = (const float*)d_in[9];
    const float* W4    = (const float*)d_in[10];
    const float* b4    = (const float*)d_in[11];
    float* out = (float*)d_out;

    float *xp, *partp;
    __half *base0h, *tvech, *h254, *h255, *actA, *actB, *w16;
    cudaGetSymbolAddress((void**)&base0h, g_base0h);
    cudaGetSymbolAddress((void**)&tvech,  g_tvech);
    cudaGetSymbolAddress((void**)&h254,   g_w254h);
    cudaGetSymbolAddress((void**)&h255,   g_w255h);
    cudaGetSymbolAddress((void**)&xp,     g_x);
    cudaGetSymbolAddress((void**)&actA,   g_actA);
    cudaGetSymbolAddress((void**)&actB,   g_actB);
    cudaGetSymbolAddress((void**)&w16,    g_w16);
    cudaGetSymbolAddress((void**)&partp,  g_part);

    static bool attr_set = false;
    if (!attr_set) {
        cudaFuncSetAttribute(gemm_hmma, cudaFuncAttributeMaxDynamicSharedMemorySize,
                             GSMEM_TOTAL);
        cudaFuncSetAttribute(gemm_hmma_last, cudaFuncAttributeMaxDynamicSharedMemorySize,
                             GSMEM_TOTAL);
        attr_set = true;
    }

    // one-time prep (normal launches)
    cudaMemcpyAsync(xp, x0, B_ * C_ * sizeof(float), cudaMemcpyDeviceToDevice);
    wconv_kernel<<<dim3(32, 32, 3), dim3(32, 8)>>>(W1, W2, W3, w16);
    tvec_kernel<<<dim3(NSTEPS, 8), 128>>>(W0, tvech);
    wrow_kernel<<<4, 256>>>(W0 + (size_t)254 * H_, W0 + (size_t)255 * H_, h254, h255);
    sgemm_kernel<<<dim3(H_ / BN, B_ / BM), 256>>>(state, S_, W0, H_, b0, base0h, H_, S_);

    __half* wl0 = w16 + 0 * (size_t)H_ * H_;
    __half* wl1 = w16 + 1 * (size_t)H_ * H_;
    __half* wl2 = w16 + 2 * (size_t)H_ * H_;

    dim3 ggrid(H_ / GBN, B_ / GBM);  // (16, 8) = 128 CTAs
    layer0_act<<<B_ / 2, 256>>>(base0h, tvech, h254, h255, xp, actA);
    for (int i = 0; i < NSTEPS; i++) {
        launch_pdl(gemm_hmma, ggrid, dim3(256), (size_t)GSMEM_TOTAL,
                   (const __half*)actA, (const __half*)wl0, b1, actB);
        launch_pdl(gemm_hmma, ggrid, dim3(256), (size_t)GSMEM_TOTAL,
                   (const __half*)actB, (const __half*)wl1, b2, actA);
        launch_pdl(gemm_hmma_last, ggrid, dim3(256), (size_t)GSMEM_TOTAL,
                   (const __half*)actA, (const __half*)wl2, b3, W4, partp);
        if (i + 1 < NSTEPS) {
            launch_pdl(step_fuse, dim3(B_ / 2), dim3(256), (size_t)0,
                       (const float*)partp, b4, xp, (const __half*)base0h,
                       (const __half*)(tvech + (size_t)(i + 1) * H_), h254, h255, actA);
        } else {
            launch_pdl(out_euler, dim3(B_ / 8), dim3(256), (size_t)0,
                       (const float*)partp, b4, (const float*)xp, out);
        }
    }
}